// round 6
// baseline (speedup 1.0000x reference)
#include <cuda_runtime.h>

// Problem constants
#define Bn     8192
#define Tb     16        // batch rows per block (full chain held in smem)
#define F0n    2048
#define En     512
#define OUTn   2048
#define Wn     3584      // F0 + 3*E
#define NNZ_E  8192
#define NNZ_M  16384
#define NBLK   (Bn / Tb) // 512
#define NTHR   1024      // 32 warps

// ---------------------------------------------------------------------------
// Device scratch (no allocation allowed)
// ---------------------------------------------------------------------------
__device__ int  g_ptr[4 * 2049];
__device__ int2 g_ent[4 * 16384];   // packed {col, float_bits(val)}, CSR order

// ---------------------------------------------------------------------------
// CSR build: one block per weight (3 embed + main). smem count/scan/scatter.
// ---------------------------------------------------------------------------
#define BLD 512
__global__ void build_k(const int* __restrict__ r0, const int* __restrict__ c0, const float* __restrict__ v0,
                        const int* __restrict__ r1, const int* __restrict__ c1, const float* __restrict__ v1,
                        const int* __restrict__ r2, const int* __restrict__ c2, const float* __restrict__ v2,
                        const int* __restrict__ rm, const int* __restrict__ cm, const float* __restrict__ vm) {
    __shared__ int cnt[2048];
    __shared__ int cur[2048];
    __shared__ int part[BLD];
    int w = blockIdx.x;
    int t = threadIdx.x;

    const int*   rows = (w == 0) ? r0 : (w == 1) ? r1 : (w == 2) ? r2 : rm;
    const int*   cols = (w == 0) ? c0 : (w == 1) ? c1 : (w == 2) ? c2 : cm;
    const float* vals = (w == 0) ? v0 : (w == 1) ? v1 : (w == 2) ? v2 : vm;
    int nrows = (w < 3) ? En : OUTn;
    int nnz   = (w < 3) ? NNZ_E : NNZ_M;
    int per   = nrows / BLD;             // 1 or 4

    for (int i = t; i < 2048; i += BLD) cnt[i] = 0;
    __syncthreads();
    for (int k = t; k < nnz; k += BLD) atomicAdd(&cnt[rows[k]], 1);
    __syncthreads();

    int sum = 0;
    for (int j = 0; j < per; j++) sum += cnt[t * per + j];
    part[t] = sum;
    __syncthreads();
    for (int off = 1; off < BLD; off <<= 1) {
        int v = (t >= off) ? part[t - off] : 0;
        __syncthreads();
        part[t] += v;
        __syncthreads();
    }
    int run = part[t] - sum;
    for (int j = 0; j < per; j++) {
        int i = t * per + j;
        g_ptr[w * 2049 + i] = run;
        cur[i] = run;
        run += cnt[i];
    }
    if (t == BLD - 1) g_ptr[w * 2049 + nrows] = part[BLD - 1];
    __syncthreads();

    for (int k = t; k < nnz; k += BLD) {
        int p = atomicAdd(&cur[rows[k]], 1);
        g_ent[w * 16384 + p] = make_int2(cols[k], __float_as_int(vals[k]));
    }
}

// ---------------------------------------------------------------------------
// Warp-level row accumulator over feature-major smem h[col][16].
// lane = slot*4 + b4 : 8 entry-slots, 4 float4 batch-quads.
// Returns row sum as float4 in ALL lanes (xor-reduced over slots).
// ---------------------------------------------------------------------------
__device__ __forceinline__ float4 row_acc(const int2* __restrict__ ent,
                                          int s, int e,
                                          const float* __restrict__ hm,
                                          int slot, int b4) {
    float4 acc = make_float4(0.f, 0.f, 0.f, 0.f);
    for (int k = s; k < e; k += 8) {
        int kk = k + slot;
        int kc = (kk < e) ? kk : (e - 1);
        int2 en = __ldg(ent + kc);
        float v = (kk < e) ? __int_as_float(en.y) : 0.f;
        float4 hv = *reinterpret_cast<const float4*>(hm + en.x * 16 + b4 * 4);
        acc.x += v * hv.x;
        acc.y += v * hv.y;
        acc.z += v * hv.z;
        acc.w += v * hv.w;
    }
#pragma unroll
    for (int off = 4; off < 32; off <<= 1) {
        acc.x += __shfl_xor_sync(0xffffffffu, acc.x, off);
        acc.y += __shfl_xor_sync(0xffffffffu, acc.y, off);
        acc.z += __shfl_xor_sync(0xffffffffu, acc.z, off);
        acc.w += __shfl_xor_sync(0xffffffffu, acc.w, off);
    }
    return acc;
}

// ---------------------------------------------------------------------------
// Fused chain kernel, v4: feature-major smem h[3584][16] (64B per feature).
// One LDS.128 serves 8 entries x 16 batch rows. Warp-uniform CSR rows.
// ---------------------------------------------------------------------------
#define SMEM_BYTES (Wn * Tb * 4)

__global__ void __launch_bounds__(NTHR, 1) fused_k(const float* __restrict__ x,
                                                   float* __restrict__ out) {
    extern __shared__ float sh[];        // h[col][16]

    int t    = threadIdx.x;
    int wid  = t >> 5;                   // 0..31
    int lane = t & 31;
    int slot = lane >> 2;                // entry slot 0..7
    int b4   = lane & 3;                 // batch quad 0..3
    int b0   = blockIdx.x * Tb;

    // ---- x load + transpose to h[f][b], staged through the (unwritten)
    //      embed region of smem. 64-feature chunks, all 1024 threads. ----
    {
        float* stage = sh + (size_t)F0n * 16;      // 16 rows x 66 floats
        for (int fc = 0; fc < F0n; fc += 64) {
            int bb = t >> 6;                       // 0..15
            int fi = t & 63;
            stage[bb * 66 + fi] = x[(size_t)(b0 + bb) * F0n + fc + fi];
            __syncthreads();
            int fi2 = t >> 4;                      // 0..63
            int bb2 = t & 15;
            sh[(size_t)(fc + fi2) * 16 + bb2] = stage[bb2 * 66 + fi2];
            __syncthreads();
        }
    }

    // ---- three embed levels: 16 rows per warp ----
    for (int lev = 0; lev < 3; lev++) {
        int fo = F0n + lev * En;
        const int*  lptr = g_ptr + lev * 2049;
        const int2* ent  = g_ent + lev * 16384;
#pragma unroll 1
        for (int pr = 0; pr < 16; pr++) {
            int r = wid * 16 + pr;
            int s = __ldg(lptr + r);
            int e = __ldg(lptr + r + 1);
            float4 acc = row_acc(ent, s, e, sh, slot, b4);
            if (slot == 0)
                *reinterpret_cast<float4*>(sh + (size_t)(fo + r) * 16 + b4 * 4) = acc;
        }
        __syncthreads();
    }

    // ---- MAIN: warp owns 64 rows; 16-row register banks; no barriers ----
    const int*  mptr = g_ptr + 3 * 2049;
    const int2* ment = g_ent + 3 * 16384;
    int comp = slot & 3;
    int bmy  = b4 * 4 + comp;            // lanes 0..15 cover all 16 b's
    float* outp = out + (size_t)(b0 + bmy) * OUTn;
#pragma unroll 1
    for (int grp = 0; grp < 4; grp++) {
        int r0 = wid * 64 + grp * 16;
        float a[16];
#pragma unroll
        for (int j = 0; j < 16; j++) {
            int r = r0 + j;
            int s = __ldg(mptr + r);
            int e = __ldg(mptr + r + 1);
            float4 acc = row_acc(ment, s, e, sh, slot, b4);
            a[j] = (comp == 0) ? acc.x : (comp == 1) ? acc.y
                 : (comp == 2) ? acc.z : acc.w;
        }
        if (lane < 16) {
            float4* o4 = reinterpret_cast<float4*>(outp + r0);
            o4[0] = make_float4(a[0],  a[1],  a[2],  a[3]);
            o4[1] = make_float4(a[4],  a[5],  a[6],  a[7]);
            o4[2] = make_float4(a[8],  a[9],  a[10], a[11]);
            o4[3] = make_float4(a[12], a[13], a[14], a[15]);
        }
    }
}

// ---------------------------------------------------------------------------
// Launch
// ---------------------------------------------------------------------------
extern "C" void kernel_launch(void* const* d_in, const int* in_sizes, int n_in,
                              void* d_out, int out_size) {
    const float* x   = (const float*)d_in[0];
    const int*   er0 = (const int*)d_in[1];
    const int*   ec0 = (const int*)d_in[2];
    const float* ev0 = (const float*)d_in[3];
    const int*   er1 = (const int*)d_in[4];
    const int*   ec1 = (const int*)d_in[5];
    const float* ev1 = (const float*)d_in[6];
    const int*   er2 = (const int*)d_in[7];
    const int*   ec2 = (const int*)d_in[8];
    const float* ev2 = (const float*)d_in[9];
    const int*   mr  = (const int*)d_in[10];
    const int*   mc  = (const int*)d_in[11];
    const float* mv  = (const float*)d_in[12];
    float* out = (float*)d_out;

    static int attr_done = 0;
    if (!attr_done) {
        cudaFuncSetAttribute(fused_k, cudaFuncAttributeMaxDynamicSharedMemorySize,
                             SMEM_BYTES);
        attr_done = 1;
    }

    build_k<<<4, BLD>>>(er0, ec0, ev0, er1, ec1, ev1, er2, ec2, ev2, mr, mc, mv);
    fused_k<<<NBLK, NTHR, SMEM_BYTES>>>(x, out);
}

// round 7
// speedup vs baseline: 1.0588x; 1.0588x over previous
#include <cuda_runtime.h>

// Problem constants
#define Bn     8192
#define Tb     16        // batch rows per block (full chain held in smem)
#define F0n    2048
#define En     512
#define OUTn   2048
#define Wn     3584      // F0 + 3*E
#define HST    3585      // h stride (odd mod 32 -> conflict-free, no swizzle)
#define NNZ_E  8192
#define NNZ_M  16384
#define NBLK   (Bn / Tb) // 512
#define NTHR   1024      // 32 warps

// Entry storage: rows padded to multiples of 8 entries (zero pads).
// capacities: embed 16384 each (<= 8192+7*512), main 32768 (<= 16384+7*2048)
#define EB0 0
#define EB1 16384
#define EB2 32768
#define EBM 49152
#define ENT_TOT 81920    // int2 entries
__device__ int4 g_ent4[ENT_TOT / 2];   // 16B-aligned entry storage
__device__ int  g_ptr[4 * 2049];

// ---------------------------------------------------------------------------
// Zero entry storage (pads must be zero every launch)
// ---------------------------------------------------------------------------
__global__ void zero_ent_k() {
    int i = blockIdx.x * blockDim.x + threadIdx.x;
    if (i < ENT_TOT / 2) g_ent4[i] = make_int4(0, 0, 0, 0);
}

// ---------------------------------------------------------------------------
// CSR build with row padding to multiple of 8. One block per weight.
// ---------------------------------------------------------------------------
#define BLD 512
__global__ void build_k(const int* __restrict__ r0, const int* __restrict__ c0, const float* __restrict__ v0,
                        const int* __restrict__ r1, const int* __restrict__ c1, const float* __restrict__ v1,
                        const int* __restrict__ r2, const int* __restrict__ c2, const float* __restrict__ v2,
                        const int* __restrict__ rm, const int* __restrict__ cm, const float* __restrict__ vm) {
    __shared__ int cnt[2048];
    __shared__ int cur[2048];
    __shared__ int part[BLD];
    int w = blockIdx.x;
    int t = threadIdx.x;

    const int*   rows = (w == 0) ? r0 : (w == 1) ? r1 : (w == 2) ? r2 : rm;
    const int*   cols = (w == 0) ? c0 : (w == 1) ? c1 : (w == 2) ? c2 : cm;
    const float* vals = (w == 0) ? v0 : (w == 1) ? v1 : (w == 2) ? v2 : vm;
    int nrows = (w < 3) ? En : OUTn;
    int nnz   = (w < 3) ? NNZ_E : NNZ_M;
    int ebase = (w == 0) ? EB0 : (w == 1) ? EB1 : (w == 2) ? EB2 : EBM;
    int per   = nrows / BLD;             // 1 or 4
    int2* ge  = reinterpret_cast<int2*>(g_ent4) + ebase;

    for (int i = t; i < 2048; i += BLD) cnt[i] = 0;
    __syncthreads();
    for (int k = t; k < nnz; k += BLD) atomicAdd(&cnt[rows[k]], 1);
    __syncthreads();

    // padded counts, scan
    int pad[4];
    int sum = 0;
    for (int j = 0; j < per; j++) {
        pad[j] = (cnt[t * per + j] + 7) & ~7;
        sum += pad[j];
    }
    part[t] = sum;
    __syncthreads();
    for (int off = 1; off < BLD; off <<= 1) {
        int v = (t >= off) ? part[t - off] : 0;
        __syncthreads();
        part[t] += v;
        __syncthreads();
    }
    int run = part[t] - sum;
    for (int j = 0; j < per; j++) {
        int i = t * per + j;
        g_ptr[w * 2049 + i] = run;
        cur[i] = run;
        run += pad[j];
    }
    if (t == BLD - 1) g_ptr[w * 2049 + nrows] = part[BLD - 1];
    __syncthreads();

    for (int k = t; k < nnz; k += BLD) {
        int p = atomicAdd(&cur[rows[k]], 1);
        ge[p] = make_int2(cols[k], __float_as_int(vals[k]));
    }
}

// ---------------------------------------------------------------------------
// Dual-row accumulator: int4 entry loads (2 entries each), unroll-2.
// pA/pB point at this half's stream (already kh-offset); nA/nB = int4 counts
// (even). hb = sh + b*HST.
// ---------------------------------------------------------------------------
__device__ __forceinline__ void row_pair4(const int4* __restrict__ pA, int nA,
                                          const int4* __restrict__ pB, int nB,
                                          const float* __restrict__ hb,
                                          float& oA, float& oB) {
    float a = 0.f, c = 0.f;
    int i = 0, j = 0;
    while (i + 1 < nA && j + 1 < nB) {
        int4 x0 = __ldg(pA + i);
        int4 x1 = __ldg(pA + i + 1);
        int4 y0 = __ldg(pB + j);
        int4 y1 = __ldg(pB + j + 1);
        a += __int_as_float(x0.y) * hb[x0.x];
        c += __int_as_float(y0.y) * hb[y0.x];
        a += __int_as_float(x0.w) * hb[x0.z];
        c += __int_as_float(y0.w) * hb[y0.z];
        a += __int_as_float(x1.y) * hb[x1.x];
        c += __int_as_float(y1.y) * hb[y1.x];
        a += __int_as_float(x1.w) * hb[x1.z];
        c += __int_as_float(y1.w) * hb[y1.z];
        i += 2; j += 2;
    }
    while (i + 1 < nA) {
        int4 x0 = __ldg(pA + i);
        int4 x1 = __ldg(pA + i + 1);
        a += __int_as_float(x0.y) * hb[x0.x];
        a += __int_as_float(x0.w) * hb[x0.z];
        a += __int_as_float(x1.y) * hb[x1.x];
        a += __int_as_float(x1.w) * hb[x1.z];
        i += 2;
    }
    while (j + 1 < nB) {
        int4 y0 = __ldg(pB + j);
        int4 y1 = __ldg(pB + j + 1);
        c += __int_as_float(y0.y) * hb[y0.x];
        c += __int_as_float(y0.w) * hb[y0.z];
        c += __int_as_float(y1.y) * hb[y1.x];
        c += __int_as_float(y1.w) * hb[y1.z];
        j += 2;
    }
    oA = a; oB = c;
}

// ---------------------------------------------------------------------------
// Fused chain kernel, v5: batch-major h[b][col] at stride 3585 (no swizzle).
// lane -> (b = lane&15, kh = lane>>4). Warp-uniform row pairs, int4 entries.
// MAIN: warp owns 64 rows, register banks, coalesced float4 out, no barriers.
// ---------------------------------------------------------------------------
#define SMEM_BYTES (Tb * HST * 4)

__global__ void __launch_bounds__(NTHR, 1) fused_k(const float* __restrict__ x,
                                                   float* __restrict__ out) {
    extern __shared__ float sh[];

    int t    = threadIdx.x;
    int wid  = t >> 5;                  // 0..31
    int lane = t & 31;
    int kh   = lane >> 4;               // entry-stream half
    int b    = lane & 15;               // batch row within tile
    int b0   = blockIdx.x * Tb;

    // ---- x tile load: scalar, coalesced, conflict-free ----
    for (int i = t; i < Tb * F0n; i += NTHR) {
        int br = i >> 11;                // / F0n
        int f  = i & (F0n - 1);
        sh[br * HST + f] = x[(size_t)(b0 + br) * F0n + f];
    }
    __syncthreads();

    const float* hb = sh + b * HST;
    float*       hw = sh + b * HST;
    const int2*  ge = reinterpret_cast<const int2*>(g_ent4);

    // ---- three embed levels: 16 rows/warp as 8 pairs ----
    for (int lev = 0; lev < 3; lev++) {
        int fo = F0n + lev * En;
        const int*  lptr = g_ptr + lev * 2049;
        const int2* ent  = ge + lev * 16384;
#pragma unroll 1
        for (int pr = 0; pr < 8; pr++) {
            int r  = wid * 16 + pr * 2;
            int sA = __ldg(lptr + r);
            int sB = __ldg(lptr + r + 1);
            int eB = __ldg(lptr + r + 2);
            int hA = (sB - sA) >> 1;     // half length (entries, mult of 4)
            int hB = (eB - sB) >> 1;
            const int4* pA = reinterpret_cast<const int4*>(ent + sA + kh * hA);
            const int4* pB = reinterpret_cast<const int4*>(ent + sB + kh * hB);
            float vA, vB;
            row_pair4(pA, hA >> 1, pB, hB >> 1, hb, vA, vB);
            vA += __shfl_xor_sync(0xffffffffu, vA, 16);
            vB += __shfl_xor_sync(0xffffffffu, vB, 16);
            if (kh == 0) {
                hw[fo + r]     = vA;
                hw[fo + r + 1] = vB;
            }
        }
        __syncthreads();
    }

    // ---- MAIN: warp owns rows [wid*64, wid*64+64), no barriers ----
    const int*  mptr = g_ptr + 3 * 2049;
    const int2* ment = ge + EBM;
    float* outb = out + (size_t)(b0 + b) * OUTn;
#pragma unroll 1
    for (int grp = 0; grp < 4; grp++) {
        int rb = wid * 64 + grp * 16;
        float a[16];
#pragma unroll
        for (int jp = 0; jp < 8; jp++) {
            int r  = rb + jp * 2;
            int sA = __ldg(mptr + r);
            int sB = __ldg(mptr + r + 1);
            int eB = __ldg(mptr + r + 2);
            int hA = (sB - sA) >> 1;
            int hB = (eB - sB) >> 1;
            const int4* pA = reinterpret_cast<const int4*>(ment + sA + kh * hA);
            const int4* pB = reinterpret_cast<const int4*>(ment + sB + kh * hB);
            float vA, vB;
            row_pair4(pA, hA >> 1, pB, hB >> 1, hb, vA, vB);
            vA += __shfl_xor_sync(0xffffffffu, vA, 16);
            vB += __shfl_xor_sync(0xffffffffu, vB, 16);
            a[jp * 2]     = vA;
            a[jp * 2 + 1] = vB;
        }
        if (kh == 0) {
            float4* o4 = reinterpret_cast<float4*>(outb + rb);
            o4[0] = make_float4(a[0],  a[1],  a[2],  a[3]);
            o4[1] = make_float4(a[4],  a[5],  a[6],  a[7]);
            o4[2] = make_float4(a[8],  a[9],  a[10], a[11]);
            o4[3] = make_float4(a[12], a[13], a[14], a[15]);
        }
    }
}

// ---------------------------------------------------------------------------
// Launch
// ---------------------------------------------------------------------------
extern "C" void kernel_launch(void* const* d_in, const int* in_sizes, int n_in,
                              void* d_out, int out_size) {
    const float* x   = (const float*)d_in[0];
    const int*   er0 = (const int*)d_in[1];
    const int*   ec0 = (const int*)d_in[2];
    const float* ev0 = (const float*)d_in[3];
    const int*   er1 = (const int*)d_in[4];
    const int*   ec1 = (const int*)d_in[5];
    const float* ev1 = (const float*)d_in[6];
    const int*   er2 = (const int*)d_in[7];
    const int*   ec2 = (const int*)d_in[8];
    const float* ev2 = (const float*)d_in[9];
    const int*   mr  = (const int*)d_in[10];
    const int*   mc  = (const int*)d_in[11];
    const float* mv  = (const float*)d_in[12];
    float* out = (float*)d_out;

    static int attr_done = 0;
    if (!attr_done) {
        cudaFuncSetAttribute(fused_k, cudaFuncAttributeMaxDynamicSharedMemorySize,
                             SMEM_BYTES);
        attr_done = 1;
    }

    zero_ent_k<<<(ENT_TOT / 2 + 255) / 256, 256>>>();
    build_k<<<4, BLD>>>(er0, ec0, ev0, er1, ec1, ev1, er2, ec2, ev2, mr, mc, mv);
    fused_k<<<NBLK, NTHR, SMEM_BYTES>>>(x, out);
}

// round 8
// speedup vs baseline: 1.7591x; 1.6613x over previous
#include <cuda_runtime.h>
#include <cuda_fp16.h>

// Problem constants
#define Bn     8192
#define Tb     32        // batch rows per block (fp16 chain in smem)
#define HPR    16        // half2 "batch-pair" rows = Tb/2
#define F0n    2048
#define En     512
#define OUTn   2048
#define Wn     3584      // F0 + 3*E
#define NNZ_E  8192
#define NNZ_M  16384
#define NBLK   (Bn / Tb) // 256
#define NTHR   1024      // 32 warps

// ---------------------------------------------------------------------------
// Device scratch (no allocation allowed)
// ---------------------------------------------------------------------------
__device__ int  g_ptr[4 * 2049];
__device__ int2 g_ent[4 * 16384];   // packed {col, float_bits(val)}, CSR order

// ---------------------------------------------------------------------------
// CSR build: one block per weight (3 embed + main). smem count/scan/scatter.
// ---------------------------------------------------------------------------
#define BLD 512
__global__ void build_k(const int* __restrict__ r0, const int* __restrict__ c0, const float* __restrict__ v0,
                        const int* __restrict__ r1, const int* __restrict__ c1, const float* __restrict__ v1,
                        const int* __restrict__ r2, const int* __restrict__ c2, const float* __restrict__ v2,
                        const int* __restrict__ rm, const int* __restrict__ cm, const float* __restrict__ vm) {
    __shared__ int cnt[2048];
    __shared__ int cur[2048];
    __shared__ int part[BLD];
    int w = blockIdx.x;
    int t = threadIdx.x;

    const int*   rows = (w == 0) ? r0 : (w == 1) ? r1 : (w == 2) ? r2 : rm;
    const int*   cols = (w == 0) ? c0 : (w == 1) ? c1 : (w == 2) ? c2 : cm;
    const float* vals = (w == 0) ? v0 : (w == 1) ? v1 : (w == 2) ? v2 : vm;
    int nrows = (w < 3) ? En : OUTn;
    int nnz   = (w < 3) ? NNZ_E : NNZ_M;
    int per   = nrows / BLD;             // 1 or 4

    for (int i = t; i < 2048; i += BLD) cnt[i] = 0;
    __syncthreads();
    for (int k = t; k < nnz; k += BLD) atomicAdd(&cnt[rows[k]], 1);
    __syncthreads();

    int sum = 0;
    for (int j = 0; j < per; j++) sum += cnt[t * per + j];
    part[t] = sum;
    __syncthreads();
    for (int off = 1; off < BLD; off <<= 1) {
        int v = (t >= off) ? part[t - off] : 0;
        __syncthreads();
        part[t] += v;
        __syncthreads();
    }
    int run = part[t] - sum;
    for (int j = 0; j < per; j++) {
        int i = t * per + j;
        g_ptr[w * 2049 + i] = run;
        cur[i] = run;
        run += cnt[i];
    }
    if (t == BLD - 1) g_ptr[w * 2049 + nrows] = part[BLD - 1];
    __syncthreads();

    for (int k = t; k < nnz; k += BLD) {
        int p = atomicAdd(&cur[rows[k]], 1);
        g_ent[w * 16384 + p] = make_int2(cols[k], __float_as_int(vals[k]));
    }
}

// ---------------------------------------------------------------------------
// Dual-row accumulator over half2 activations, fp32 accumulation.
// Half kh walks its parity of each row's entry list (stride 2).
// hb2 = per-lane batch-pair row (swizzled col ^ bp indexing by caller macro).
// ---------------------------------------------------------------------------
__device__ __forceinline__ void row_pair_h(const int2* __restrict__ ent,
                                           int sA, int eA, int sB, int eB,
                                           const __half2* __restrict__ hb2,
                                           int bp, int kh,
                                           float2& oA, float2& oB) {
    float2 a = make_float2(0.f, 0.f), c = make_float2(0.f, 0.f);
    int kA = sA + kh, kB = sB + kh;
    while (kA + 6 < eA && kB + 6 < eB) {
        int2 x0 = __ldg(ent + kA);
        int2 x1 = __ldg(ent + kA + 2);
        int2 x2 = __ldg(ent + kA + 4);
        int2 x3 = __ldg(ent + kA + 6);
        int2 y0 = __ldg(ent + kB);
        int2 y1 = __ldg(ent + kB + 2);
        int2 y2 = __ldg(ent + kB + 4);
        int2 y3 = __ldg(ent + kB + 6);
        float2 h0 = __half22float2(hb2[x0.x ^ bp]);
        float2 g0 = __half22float2(hb2[y0.x ^ bp]);
        float2 h1 = __half22float2(hb2[x1.x ^ bp]);
        float2 g1 = __half22float2(hb2[y1.x ^ bp]);
        float2 h2 = __half22float2(hb2[x2.x ^ bp]);
        float2 g2 = __half22float2(hb2[y2.x ^ bp]);
        float2 h3 = __half22float2(hb2[x3.x ^ bp]);
        float2 g3 = __half22float2(hb2[y3.x ^ bp]);
        float v0 = __int_as_float(x0.y), w0 = __int_as_float(y0.y);
        float v1 = __int_as_float(x1.y), w1 = __int_as_float(y1.y);
        float v2 = __int_as_float(x2.y), w2 = __int_as_float(y2.y);
        float v3 = __int_as_float(x3.y), w3 = __int_as_float(y3.y);
        a.x += v0 * h0.x; a.y += v0 * h0.y;
        c.x += w0 * g0.x; c.y += w0 * g0.y;
        a.x += v1 * h1.x; a.y += v1 * h1.y;
        c.x += w1 * g1.x; c.y += w1 * g1.y;
        a.x += v2 * h2.x; a.y += v2 * h2.y;
        c.x += w2 * g2.x; c.y += w2 * g2.y;
        a.x += v3 * h3.x; a.y += v3 * h3.y;
        c.x += w3 * g3.x; c.y += w3 * g3.y;
        kA += 8; kB += 8;
    }
    while (kA + 6 < eA) {
        int2 x0 = __ldg(ent + kA);
        int2 x1 = __ldg(ent + kA + 2);
        int2 x2 = __ldg(ent + kA + 4);
        int2 x3 = __ldg(ent + kA + 6);
        float2 h0 = __half22float2(hb2[x0.x ^ bp]);
        float2 h1 = __half22float2(hb2[x1.x ^ bp]);
        float2 h2 = __half22float2(hb2[x2.x ^ bp]);
        float2 h3 = __half22float2(hb2[x3.x ^ bp]);
        a.x += __int_as_float(x0.y) * h0.x; a.y += __int_as_float(x0.y) * h0.y;
        a.x += __int_as_float(x1.y) * h1.x; a.y += __int_as_float(x1.y) * h1.y;
        a.x += __int_as_float(x2.y) * h2.x; a.y += __int_as_float(x2.y) * h2.y;
        a.x += __int_as_float(x3.y) * h3.x; a.y += __int_as_float(x3.y) * h3.y;
        kA += 8;
    }
    while (kB + 6 < eB) {
        int2 y0 = __ldg(ent + kB);
        int2 y1 = __ldg(ent + kB + 2);
        int2 y2 = __ldg(ent + kB + 4);
        int2 y3 = __ldg(ent + kB + 6);
        float2 g0 = __half22float2(hb2[y0.x ^ bp]);
        float2 g1 = __half22float2(hb2[y1.x ^ bp]);
        float2 g2 = __half22float2(hb2[y2.x ^ bp]);
        float2 g3 = __half22float2(hb2[y3.x ^ bp]);
        c.x += __int_as_float(y0.y) * g0.x; c.y += __int_as_float(y0.y) * g0.y;
        c.x += __int_as_float(y1.y) * g1.x; c.y += __int_as_float(y1.y) * g1.y;
        c.x += __int_as_float(y2.y) * g2.x; c.y += __int_as_float(y2.y) * g2.y;
        c.x += __int_as_float(y3.y) * g3.x; c.y += __int_as_float(y3.y) * g3.y;
        kB += 8;
    }
    for (; kA < eA; kA += 2) {
        int2 x = __ldg(ent + kA);
        float2 h = __half22float2(hb2[x.x ^ bp]);
        a.x += __int_as_float(x.y) * h.x; a.y += __int_as_float(x.y) * h.y;
    }
    for (; kB < eB; kB += 2) {
        int2 y = __ldg(ent + kB);
        float2 g = __half22float2(hb2[y.x ^ bp]);
        c.x += __int_as_float(y.y) * g.x; c.y += __int_as_float(y.y) * g.y;
    }
    oA = a; oB = c;
}

// ---------------------------------------------------------------------------
// Fused chain kernel, v6: Tb=32 batch rows as 16 half2 batch-pair rows.
// h2[bp][col^bp], stride 3584 words (same bank geometry as proven fp32 v3).
// lane -> (bp = lane&15, kh = lane>>4). fp32 accumulate, fp16 store.
// MAIN: warp owns 64 rows; 8-row register groups; all 32 lanes write out.
// ---------------------------------------------------------------------------
#define SMEM_BYTES (HPR * Wn * 4)

__global__ void __launch_bounds__(NTHR, 1) fused_k(const float* __restrict__ x,
                                                   float* __restrict__ out) {
    extern __shared__ __half2 sh2[];

    int t    = threadIdx.x;
    int wid  = t >> 5;                  // 0..31
    int lane = t & 31;
    int kh   = lane >> 4;               // entry-stream half
    int bp   = lane & 15;               // batch-pair row
    int b0   = blockIdx.x * Tb;

    // ---- x tile load: pack 2 batch rows into half2, swizzled ----
    for (int i = t; i < HPR * F0n; i += NTHR) {
        int p = i >> 11;                 // batch pair 0..15
        int f = i & (F0n - 1);
        float v0 = x[(size_t)(b0 + 2 * p)     * F0n + f];
        float v1 = x[(size_t)(b0 + 2 * p + 1) * F0n + f];
        sh2[(size_t)p * Wn + (f ^ p)] = __floats2half2_rn(v0, v1);
    }
    __syncthreads();

    const __half2* hb2 = sh2 + (size_t)bp * Wn;
    __half2*       hw2 = sh2 + (size_t)bp * Wn;

    // ---- three embed levels: 16 rows/warp as 8 pairs ----
    for (int lev = 0; lev < 3; lev++) {
        int fo = F0n + lev * En;
        const int*  lptr = g_ptr + lev * 2049;
        const int2* ent  = g_ent + lev * 16384;
#pragma unroll 1
        for (int pr = 0; pr < 8; pr++) {
            int r  = wid * 16 + pr * 2;
            int sA = __ldg(lptr + r);
            int sB = __ldg(lptr + r + 1);
            int eB = __ldg(lptr + r + 2);
            float2 vA, vB;
            row_pair_h(ent, sA, sB, sB, eB, hb2, bp, kh, vA, vB);
            vA.x += __shfl_xor_sync(0xffffffffu, vA.x, 16);
            vA.y += __shfl_xor_sync(0xffffffffu, vA.y, 16);
            vB.x += __shfl_xor_sync(0xffffffffu, vB.x, 16);
            vB.y += __shfl_xor_sync(0xffffffffu, vB.y, 16);
            if (kh == 0) {
                hw2[(fo + r)     ^ bp] = __floats2half2_rn(vA.x, vA.y);
                hw2[(fo + r + 1) ^ bp] = __floats2half2_rn(vB.x, vB.y);
            }
        }
        __syncthreads();
    }

    // ---- MAIN: warp owns rows [wid*64, wid*64+64) in 8 groups of 8 ----
    const int*  mptr = g_ptr + 3 * 2049;
    const int2* ment = g_ent + 3 * 16384;
    int bl = 2 * bp + kh;                // this lane's output batch row
    float* outb = out + (size_t)(b0 + bl) * OUTn;
#pragma unroll 1
    for (int grp = 0; grp < 8; grp++) {
        int rb = wid * 64 + grp * 8;
        float a[8];
#pragma unroll
        for (int jp = 0; jp < 4; jp++) {
            int r  = rb + jp * 2;
            int sA = __ldg(mptr + r);
            int sB = __ldg(mptr + r + 1);
            int eB = __ldg(mptr + r + 2);
            float2 vA, vB;
            row_pair_h(ment, sA, sB, sB, eB, hb2, bp, kh, vA, vB);
            vA.x += __shfl_xor_sync(0xffffffffu, vA.x, 16);
            vA.y += __shfl_xor_sync(0xffffffffu, vA.y, 16);
            vB.x += __shfl_xor_sync(0xffffffffu, vB.x, 16);
            vB.y += __shfl_xor_sync(0xffffffffu, vB.y, 16);
            a[jp * 2]     = kh ? vA.y : vA.x;
            a[jp * 2 + 1] = kh ? vB.y : vB.x;
        }
        float4* o4 = reinterpret_cast<float4*>(outb + rb);
        o4[0] = make_float4(a[0], a[1], a[2], a[3]);
        o4[1] = make_float4(a[4], a[5], a[6], a[7]);
    }
}

// ---------------------------------------------------------------------------
// Launch
// ---------------------------------------------------------------------------
extern "C" void kernel_launch(void* const* d_in, const int* in_sizes, int n_in,
                              void* d_out, int out_size) {
    const float* x   = (const float*)d_in[0];
    const int*   er0 = (const int*)d_in[1];
    const int*   ec0 = (const int*)d_in[2];
    const float* ev0 = (const float*)d_in[3];
    const int*   er1 = (const int*)d_in[4];
    const int*   ec1 = (const int*)d_in[5];
    const float* ev1 = (const float*)d_in[6];
    const int*   er2 = (const int*)d_in[7];
    const int*   ec2 = (const int*)d_in[8];
    const float* ev2 = (const float*)d_in[9];
    const int*   mr  = (const int*)d_in[10];
    const int*   mc  = (const int*)d_in[11];
    const float* mv  = (const float*)d_in[12];
    float* out = (float*)d_out;

    static int attr_done = 0;
    if (!attr_done) {
        cudaFuncSetAttribute(fused_k, cudaFuncAttributeMaxDynamicSharedMemorySize,
                             SMEM_BYTES);
        attr_done = 1;
    }

    build_k<<<4, BLD>>>(er0, ec0, ev0, er1, ec1, ev1, er2, ec2, ev2, mr, mc, mv);
    fused_k<<<NBLK, NTHR, SMEM_BYTES>>>(x, out);
}